// round 17
// baseline (speedup 1.0000x reference)
#include <cuda_runtime.h>
#include <cuda_bf16.h>
#include <cuda_fp16.h>
#include <math_constants.h>
#include <cstdint>

// Problem constants
#define BSZ   2
#define SEQ   2048
#define HID   2048
#define NHEAD 32
#define HD    16
#define PROJ  512
#define MROWS (BSZ * SEQ)   // 4096
#define SCALE 0.125f
#define QPRE  (0.125f * 1.4426950408889634f)   // SCALE * log2(e)

// ---------------------------------------------------------------------------
// Persistent scratch (device globals — no allocation allowed).
// All arrays hold fp16 bit patterns (uint16 containers).
// ---------------------------------------------------------------------------
__device__ uint16_t g_IAh[(size_t)3 * MROWS * HID];   // q,k,v inputs, fp16 hi
__device__ uint16_t g_IAl[(size_t)3 * MROWS * HID];   // fp16 lo
__device__ uint16_t g_WBh[(size_t)4 * PROJ * HID];    // Wq,Wk,Wv,Wo fp16 hi
__device__ uint16_t g_WBl[(size_t)4 * PROJ * HID];    // fp16 lo
__device__ uint16_t g_Qh[MROWS * PROJ];               // fp16 single, pre-scaled
__device__ uint16_t g_Kh[MROWS * PROJ];               // fp16 hi
__device__ uint16_t g_Kl[MROWS * PROJ];               // fp16 lo
__device__ uint16_t g_Vh[MROWS * PROJ];               // fp16 single
__device__ uint16_t g_AOh[MROWS * PROJ];              // fp16 single

// ---------------------------------------------------------------------------
// Helpers
// ---------------------------------------------------------------------------
__device__ __forceinline__ void split2h(float x, float y, uint32_t& hi, uint32_t& lo) {
    __half2 h = __floats2half2_rn(x, y);
    float2 hf = __half22float2(h);
    __half2 l = __floats2half2_rn(x - hf.x, y - hf.y);
    hi = *(uint32_t*)&h;
    lo = *(uint32_t*)&l;
}

__device__ __forceinline__ void mma_f16(float* c, const uint32_t* a, const uint32_t* b) {
    asm volatile(
        "mma.sync.aligned.m16n8k16.row.col.f32.f16.f16.f32 "
        "{%0,%1,%2,%3}, {%4,%5,%6,%7}, {%8,%9}, {%0,%1,%2,%3};"
        : "+f"(c[0]), "+f"(c[1]), "+f"(c[2]), "+f"(c[3])
        : "r"(a[0]), "r"(a[1]), "r"(a[2]), "r"(a[3]), "r"(b[0]), "r"(b[1]));
}

__device__ __forceinline__ void ldsm_x4(uint32_t addr, uint32_t& r0, uint32_t& r1,
                                        uint32_t& r2, uint32_t& r3) {
    asm volatile("ldmatrix.sync.aligned.m8n8.x4.shared.b16 {%0,%1,%2,%3}, [%4];"
                 : "=r"(r0), "=r"(r1), "=r"(r2), "=r"(r3) : "r"(addr));
}
__device__ __forceinline__ void ldsm_x2t(uint32_t addr, uint32_t& r0, uint32_t& r1) {
    asm volatile("ldmatrix.sync.aligned.m8n8.x2.trans.shared.b16 {%0,%1}, [%2];"
                 : "=r"(r0), "=r"(r1) : "r"(addr));
}

__device__ __forceinline__ uint32_t smem_u32(const void* p) {
    uint32_t a;
    asm("{ .reg .u64 t; cvta.to.shared.u64 t, %1; cvt.u32.u64 %0, t; }" : "=r"(a) : "l"(p));
    return a;
}

__device__ __forceinline__ void cpasync16(uint32_t dst, const void* src) {
    asm volatile("cp.async.cg.shared.global [%0], [%1], 16;" :: "r"(dst), "l"(src) : "memory");
}
__device__ __forceinline__ void cpcommit() {
    asm volatile("cp.async.commit_group;" ::: "memory");
}
template <int N>
__device__ __forceinline__ void cpwait() {
    asm volatile("cp.async.wait_group %0;" :: "n"(N) : "memory");
}

// ---------------------------------------------------------------------------
// Fused one-time split pass: all 7 tensors -> fp16 hi/lo, ONE launch.
// ---------------------------------------------------------------------------
#define N4_IN (MROWS * HID / 4)
#define N4_W  (PROJ * HID / 4)
#define N4_TOTAL (3 * N4_IN + 4 * N4_W)

__global__ __launch_bounds__(256) void split_all_kernel(
    const float4* __restrict__ q, const float4* __restrict__ k,
    const float4* __restrict__ v, const float4* __restrict__ wq,
    const float4* __restrict__ wk, const float4* __restrict__ wv,
    const float4* __restrict__ wo) {
    const size_t i = (size_t)blockIdx.x * 256 + threadIdx.x;
    if (i >= N4_TOTAL) return;
    const float4* src;
    uint16_t *dh, *dl;
    size_t off;
    int idx;
    if (i < (size_t)3 * N4_IN) {
        const int w = (int)(i / N4_IN);
        idx = (int)(i - (size_t)w * N4_IN);
        src = (w == 0) ? q : (w == 1) ? k : v;
        dh = g_IAh; dl = g_IAl;
        off = (size_t)w * MROWS * HID;
    } else {
        const size_t j = i - (size_t)3 * N4_IN;
        const int w = (int)(j / N4_W);
        idx = (int)(j - (size_t)w * N4_W);
        src = (w == 0) ? wq : (w == 1) ? wk : (w == 2) ? wv : wo;
        dh = g_WBh; dl = g_WBl;
        off = (size_t)w * PROJ * HID;
    }
    float4 val = src[idx];
    uint32_t h01, l01, h23, l23;
    split2h(val.x, val.y, h01, l01);
    split2h(val.z, val.w, h23, l23);
    ((uint2*)(dh + off))[idx] = make_uint2(h01, h23);
    ((uint2*)(dl + off))[idx] = make_uint2(l01, l23);
}

// ===========================================================================
// f16 2-term tensor-core GEMM (A hi x B hi/lo), cp.async multi-stage.
// Epilogue modes: 0=fp32, 2=fp16 hi/lo, 3=fp16 single (x pre).
// ===========================================================================
#define GBN 128
#define GBK 32
#define GTHREADS 256
#define ROWB 80
#define TILE_BB (128 * ROWB)

template <int MT, int STAGES>
struct GemmCfg {
    static const int CTA_M  = MT * 32;
    static const int TILE_A = CTA_M * ROWB;
    static const int OFF_BH = TILE_A;
    static const int OFF_BL = TILE_A + TILE_BB;
    static const int STAGE  = TILE_A + 2 * TILE_BB;
    static const int SMEM   = STAGES * STAGE;
};

template <int MT, int STAGES>
__device__ __forceinline__ void tc_gemm_body(const uint16_t* __restrict__ Ahg,
                                             const uint16_t* __restrict__ Bhg,
                                             const uint16_t* __restrict__ Blg,
                                             float* __restrict__ Cf,
                                             uint16_t* __restrict__ Chi,
                                             uint16_t* __restrict__ Clo,
                                             int mode, float pre,
                                             int K, int N) {
    typedef GemmCfg<MT, STAGES> C;
    extern __shared__ char smem[];
    const uint32_t sb = smem_u32(smem);

    const int tid = threadIdx.x;
    const int wid = tid >> 5;
    const int lane = tid & 31;
    const int wm = wid >> 2;
    const int wn = wid & 3;
    const int gid = lane >> 2;
    const int tig = lane & 3;

    const int m0 = blockIdx.y * C::CTA_M;
    const int n0 = blockIdx.x * GBN;
    const int nc = K / GBK;

    const uint32_t a_lm = (uint32_t)((wm * (MT * 16) + (lane & 15)) * ROWB + (lane >> 4) * 16);
    const uint32_t b_lm = (uint32_t)((wn * 32 + (lane & 7) + ((lane >> 4) & 1) * 8) * ROWB
                                     + ((lane >> 3) & 1) * 16);

    float acc[MT][4][4];
#pragma unroll
    for (int mt = 0; mt < MT; mt++)
#pragma unroll
        for (int nt = 0; nt < 4; nt++)
#pragma unroll
            for (int r = 0; r < 4; r++) acc[mt][nt][r] = 0.f;

    auto issue_stage = [&](int i) {
        const uint32_t st = sb + (i % STAGES) * C::STAGE;
        const int k0 = i * GBK;
#pragma unroll
        for (int j = 0; j < MT / 2; j++) {
            const int idx = tid + j * 256;
            const int row = idx >> 2, ch = idx & 3;
            const uint32_t d = (uint32_t)(row * ROWB + ch * 16);
            const size_t ga = (size_t)(m0 + row) * K + k0 + ch * 8;
            cpasync16(st + d, Ahg + ga);
        }
#pragma unroll
        for (int j = 0; j < 2; j++) {
            const int idx = tid + j * 256;
            const int row = idx >> 2, ch = idx & 3;
            const uint32_t d = (uint32_t)(row * ROWB + ch * 16);
            const size_t gb = (size_t)(n0 + row) * K + k0 + ch * 8;
            cpasync16(st + C::OFF_BH + d, Bhg + gb);
            cpasync16(st + C::OFF_BL + d, Blg + gb);
        }
    };

#pragma unroll
    for (int s = 0; s < STAGES - 1; s++) { issue_stage(s); cpcommit(); }

    for (int i = 0; i < nc; i++) {
        if (STAGES == 3 && i + 1 < nc) cpwait<1>(); else cpwait<0>();
        __syncthreads();
        if (i + STAGES - 1 < nc) { issue_stage(i + STAGES - 1); cpcommit(); }

        const uint32_t st = sb + (i % STAGES) * C::STAGE;

#pragma unroll
        for (int ks = 0; ks < 2; ks++) {
            const uint32_t koff = ks * 32;
            uint32_t bh[4][2], bl[4][2];
            ldsm_x4(st + C::OFF_BH + b_lm + koff,
                    bh[0][0], bh[0][1], bh[1][0], bh[1][1]);
            ldsm_x4(st + C::OFF_BH + b_lm + 16 * ROWB + koff,
                    bh[2][0], bh[2][1], bh[3][0], bh[3][1]);
            ldsm_x4(st + C::OFF_BL + b_lm + koff,
                    bl[0][0], bl[0][1], bl[1][0], bl[1][1]);
            ldsm_x4(st + C::OFF_BL + b_lm + 16 * ROWB + koff,
                    bl[2][0], bl[2][1], bl[3][0], bl[3][1]);
#pragma unroll
            for (int mt = 0; mt < MT; mt++) {
                uint32_t ah[4];
                ldsm_x4(st + a_lm + mt * 16 * ROWB + koff, ah[0], ah[1], ah[2], ah[3]);
#pragma unroll
                for (int nt = 0; nt < 4; nt++) {
                    mma_f16(acc[mt][nt], ah, bh[nt]);
                    mma_f16(acc[mt][nt], ah, bl[nt]);
                }
            }
        }
    }

#pragma unroll
    for (int mt = 0; mt < MT; mt++) {
#pragma unroll
        for (int nt = 0; nt < 4; nt++) {
            const int m = m0 + wm * (MT * 16) + mt * 16 + gid;
            const int n = n0 + wn * 32 + nt * 8 + 2 * tig;
            if (mode == 0) {
                *(float2*)&Cf[(size_t)m * N + n] = make_float2(acc[mt][nt][0], acc[mt][nt][1]);
                *(float2*)&Cf[(size_t)(m + 8) * N + n] = make_float2(acc[mt][nt][2], acc[mt][nt][3]);
            } else if (mode == 2) {
                uint32_t hi, lo;
                split2h(acc[mt][nt][0], acc[mt][nt][1], hi, lo);
                *(uint32_t*)&Chi[(size_t)m * N + n] = hi;
                *(uint32_t*)&Clo[(size_t)m * N + n] = lo;
                split2h(acc[mt][nt][2], acc[mt][nt][3], hi, lo);
                *(uint32_t*)&Chi[(size_t)(m + 8) * N + n] = hi;
                *(uint32_t*)&Clo[(size_t)(m + 8) * N + n] = lo;
            } else {
                __half2 h0 = __floats2half2_rn(acc[mt][nt][0] * pre, acc[mt][nt][1] * pre);
                __half2 h1 = __floats2half2_rn(acc[mt][nt][2] * pre, acc[mt][nt][3] * pre);
                *(uint32_t*)&Chi[(size_t)m * N + n] = *(uint32_t*)&h0;
                *(uint32_t*)&Chi[(size_t)(m + 8) * N + n] = *(uint32_t*)&h1;
            }
        }
    }
}

// Projections: 64x128 tiles, 3-stage, f16 2-term.
// z: 0=Q (fp16 single, pre-scaled), 1=K (fp16 hi/lo), 2=V (fp16 single)
__global__ __launch_bounds__(GTHREADS, 2)
void proj_tc_kernel() {
    const size_t za = (size_t)blockIdx.z * MROWS * HID;
    const size_t zw = (size_t)blockIdx.z * PROJ * HID;
    uint16_t *Chi = nullptr, *Clo = nullptr;
    int mode;
    float pre = 1.f;
    if (blockIdx.z == 0)      { Chi = g_Qh; mode = 3; pre = QPRE; }
    else if (blockIdx.z == 1) { Chi = g_Kh; Clo = g_Kl; mode = 2; }
    else                      { Chi = g_Vh; mode = 3; }
    tc_gemm_body<2, 3>(g_IAh + za, g_WBh + zw, g_WBl + zw,
                       nullptr, Chi, Clo, mode, pre, HID, PROJ);
}

// Output projection: 128x128 tiles, 3-stage, f16 2-term (AO x Wo hi/lo).
__global__ __launch_bounds__(GTHREADS, 2)
void out_tc_kernel(float* __restrict__ out) {
    const size_t zw = (size_t)3 * PROJ * HID;
    tc_gemm_body<4, 3>(g_AOh, g_WBh + zw, g_WBl + zw,
                       out, nullptr, nullptr, 0, 1.f, PROJ, HID);
}

// ===========================================================================
// Tensor-core flash attention, cp.async 3-stage K/V pipeline, static-bias
// softmax. QK: f16 2-term (Q-hi x K hi/lo). P: fp16 h2exp2. PV: f16 single V.
// ===========================================================================
#define KVROW 24
#define KVROWB 48
#define KV_KH 0
#define KV_KL 6144
#define KV_VH 12288
#define KV_STAGE 18432
#define ATTN_STAGES 3
#define ATTN_SMEM (ATTN_STAGES * KV_STAGE)   // 55296

__global__ __launch_bounds__(256, 2) void attn_mma_kernel() {
    extern __shared__ char asmem[];
    const uint32_t sb = smem_u32(asmem);

    const int tid = threadIdx.x;
    const int wid = tid >> 5;
    const int lane = tid & 31;
    const int gid = lane >> 2;
    const int tig = lane & 3;
    const int h = blockIdx.y;
    const int b = blockIdx.z;
    const int q0 = blockIdx.x * 128;

    const uint32_t k_lm = (uint32_t)(((lane & 7) + ((lane >> 4) & 1) * 8) * KVROWB
                                     + ((lane >> 3) & 1) * 16);
    const uint32_t v_lm = (uint32_t)((lane & 15) * KVROWB);

    const size_t qrow = (size_t)(b * SEQ + q0 + wid * 16);
    uint32_t qh[4];
    {
        const uint16_t* Q0 = g_Qh + (qrow + gid) * PROJ + h * HD;
        const uint16_t* Q8 = g_Qh + (qrow + gid + 8) * PROJ + h * HD;
        qh[0] = *(const uint32_t*)(Q0 + 2 * tig);
        qh[1] = *(const uint32_t*)(Q8 + 2 * tig);
        qh[2] = *(const uint32_t*)(Q0 + 2 * tig + 8);
        qh[3] = *(const uint32_t*)(Q8 + 2 * tig + 8);
    }

    // per-thread K/V staging (half-row granularity)
    const int srow = tid >> 1, shalf = tid & 1;
    const uint32_t sdst = (uint32_t)(srow * KVROWB + shalf * 16);

    auto issue_kv = [&](int ti) {
        const uint32_t st = sb + (ti % ATTN_STAGES) * KV_STAGE;
        const size_t src = ((size_t)(b * SEQ + ti * 128) + srow) * PROJ + h * HD + shalf * 8;
        cpasync16(st + KV_KH + sdst, g_Kh + src);
        cpasync16(st + KV_KL + sdst, g_Kl + src);
        cpasync16(st + KV_VH + sdst, g_Vh + src);
    };

    float m0v = 0.f, m1v = 0.f;       // static bias, set at tile 0
    float l0 = 0.f, l1 = 0.f;         // per-thread partial sums
    float o[2][4];
#pragma unroll
    for (int a = 0; a < 2; a++)
#pragma unroll
        for (int r = 0; r < 4; r++) o[a][r] = 0.f;

    issue_kv(0); cpcommit();
    issue_kv(1); cpcommit();

    const int NT = SEQ / 128;   // 16
    for (int ti = 0; ti < NT; ti++) {
        if (ti + 1 < NT) cpwait<1>(); else cpwait<0>();
        __syncthreads();
        if (ti + 2 < NT) { issue_kv(ti + 2); cpcommit(); }

        const uint32_t st = sb + (ti % ATTN_STAGES) * KV_STAGE;
        const uint32_t kh_b = st + KV_KH;
        const uint32_t kl_b = st + KV_KL;
        const uint32_t vh_b = st + KV_VH;

        float sc[16][4];
#pragma unroll
        for (int p = 0; p < 8; p++) {
            uint32_t bh[2][2], bl[2][2];
            ldsm_x4(kh_b + k_lm + p * 16 * KVROWB, bh[0][0], bh[0][1], bh[1][0], bh[1][1]);
            ldsm_x4(kl_b + k_lm + p * 16 * KVROWB, bl[0][0], bl[0][1], bl[1][0], bl[1][1]);
#pragma unroll
            for (int q = 0; q < 2; q++) {
                const int nt = 2 * p + q;
                sc[nt][0] = sc[nt][1] = sc[nt][2] = sc[nt][3] = 0.f;
                mma_f16(sc[nt], qh, bh[q]);
                mma_f16(sc[nt], qh, bl[q]);
            }
        }

        if (ti == 0) {
            float mx0 = sc[0][0], mx1 = sc[0][2];
#pragma unroll
            for (int nt = 0; nt < 16; nt++) {
                mx0 = fmaxf(mx0, fmaxf(sc[nt][0], sc[nt][1]));
                mx1 = fmaxf(mx1, fmaxf(sc[nt][2], sc[nt][3]));
            }
            mx0 = fmaxf(mx0, __shfl_xor_sync(0xffffffffu, mx0, 1));
            mx0 = fmaxf(mx0, __shfl_xor_sync(0xffffffffu, mx0, 2));
            mx1 = fmaxf(mx1, __shfl_xor_sync(0xffffffffu, mx1, 1));
            mx1 = fmaxf(mx1, __shfl_xor_sync(0xffffffffu, mx1, 2));
            m0v = mx0;
            m1v = mx1;
        }

#pragma unroll
        for (int kc = 0; kc < 8; kc++) {
            __half2 p0 = h2exp2(__floats2half2_rn(sc[2 * kc][0] - m0v, sc[2 * kc][1] - m0v));
            __half2 p1 = h2exp2(__floats2half2_rn(sc[2 * kc][2] - m1v, sc[2 * kc][3] - m1v));
            __half2 p2 = h2exp2(__floats2half2_rn(sc[2 * kc + 1][0] - m0v, sc[2 * kc + 1][1] - m0v));
            __half2 p3 = h2exp2(__floats2half2_rn(sc[2 * kc + 1][2] - m1v, sc[2 * kc + 1][3] - m1v));
            float2 f;
            f = __half22float2(p0); l0 += f.x + f.y;
            f = __half22float2(p1); l1 += f.x + f.y;
            f = __half22float2(p2); l0 += f.x + f.y;
            f = __half22float2(p3); l1 += f.x + f.y;
            uint32_t a[4];
            a[0] = *(uint32_t*)&p0;
            a[1] = *(uint32_t*)&p1;
            a[2] = *(uint32_t*)&p2;
            a[3] = *(uint32_t*)&p3;

            uint32_t bvh0[2], bvh1[2];
            ldsm_x2t(vh_b + v_lm + kc * 16 * KVROWB,      bvh0[0], bvh0[1]);
            ldsm_x2t(vh_b + v_lm + kc * 16 * KVROWB + 16, bvh1[0], bvh1[1]);
            mma_f16(o[0], a, bvh0);
            mma_f16(o[1], a, bvh1);
        }
    }

    // final l reduction
    l0 += __shfl_xor_sync(0xffffffffu, l0, 1);
    l0 += __shfl_xor_sync(0xffffffffu, l0, 2);
    l1 += __shfl_xor_sync(0xffffffffu, l1, 1);
    l1 += __shfl_xor_sync(0xffffffffu, l1, 2);

    const float i0 = 1.f / l0;
    const float i1 = 1.f / l1;
    const size_t rA = (qrow + gid) * PROJ + h * HD;
    const size_t rB = (qrow + gid + 8) * PROJ + h * HD;
#pragma unroll
    for (int nt2 = 0; nt2 < 2; nt2++) {
        __half2 hA = __floats2half2_rn(o[nt2][0] * i0, o[nt2][1] * i0);
        __half2 hB = __floats2half2_rn(o[nt2][2] * i1, o[nt2][3] * i1);
        *(uint32_t*)&g_AOh[rA + nt2 * 8 + 2 * tig] = *(uint32_t*)&hA;
        *(uint32_t*)&g_AOh[rB + nt2 * 8 + 2 * tig] = *(uint32_t*)&hB;
    }
}

// ---------------------------------------------------------------------------
extern "C" void kernel_launch(void* const* d_in, const int* in_sizes, int n_in,
                              void* d_out, int out_size) {
    const float* q  = (const float*)d_in[0];
    const float* k  = (const float*)d_in[1];
    const float* v  = (const float*)d_in[2];
    const float* Wq = (const float*)d_in[3];
    const float* Wk = (const float*)d_in[4];
    const float* Wv = (const float*)d_in[5];
    const float* Wo = (const float*)d_in[6];
    float* out = (float*)d_out;

    typedef GemmCfg<2, 3> PC;
    typedef GemmCfg<4, 3> OC;
    cudaFuncSetAttribute(proj_tc_kernel,
                         cudaFuncAttributeMaxDynamicSharedMemorySize, PC::SMEM);
    cudaFuncSetAttribute(out_tc_kernel,
                         cudaFuncAttributeMaxDynamicSharedMemorySize, OC::SMEM);
    cudaFuncSetAttribute(attn_mma_kernel,
                         cudaFuncAttributeMaxDynamicSharedMemorySize, ATTN_SMEM);

    // 0) fused split: one launch (all fp16 hi/lo)
    split_all_kernel<<<(N4_TOTAL + 255) / 256, 256>>>(
        (const float4*)q, (const float4*)k, (const float4*)v,
        (const float4*)Wq, (const float4*)Wk, (const float4*)Wv, (const float4*)Wo);

    // 1) Q/K/V projections: 64x128 tiles, 3-stage, f16 2-term
    {
        dim3 grid(PROJ / GBN, MROWS / PC::CTA_M, 3);
        proj_tc_kernel<<<grid, GTHREADS, PC::SMEM>>>();
    }
    // 2) Tensor-core flash attention (f16 2-term QK, static-bias softmax)
    {
        dim3 grid(SEQ / 128, NHEAD, BSZ);
        attn_mma_kernel<<<grid, 256, ATTN_SMEM>>>();
    }
    // 3) Output projection: 128x128 tiles, 3-stage, f16 2-term
    {
        dim3 grid(HID / GBN, MROWS / OC::CTA_M);
        out_tc_kernel<<<grid, GTHREADS, OC::SMEM>>>(out);
    }
}